// round 7
// baseline (speedup 1.0000x reference)
#include <cuda_runtime.h>
#include <cuda_fp16.h>

#define NN 50000
#define EE 500000
#define GG 128
#define NCHUNK ((NN + 255) / 256)   // 196 chunks of 256

struct __align__(8) Edge { int s; float w; };

// ---------------- scratch (static device allocations; each written once per launch) ----------------
__device__ float g_deg[NN];
__device__ float g_dinv[NN];
__device__ int   g_count[NN];
__device__ int   g_rs0[NN];          // chunk-exclusive scan partials
__device__ int   g_rowstart[NN + 1];
__device__ int   g_cursor[NN];
__device__ int   g_part[NCHUNK];
__device__ Edge  g_edge[EE];

__device__ __half g_Xh[NN * 160];
__device__ __half g_T1a[NN * 160];
__device__ __half g_T2a[NN * 160];
__device__ __half g_H1[NN * 128];
__device__ __half g_T1b[NN * 128];
__device__ __half g_T2b[NN * 128];
__device__ __half g_H2[NN * 64];
__device__ __half g_T1c[NN * 64];
__device__ __half g_T2c[NN * 64];
__device__ float  g_pool[GG * 32];
__device__ float  g_cntg[GG];

__device__ unsigned g_barcnt;
__device__ volatile unsigned g_barflag;

// ---------------- grid barrier (all blocks guaranteed co-resident) ----------------
__device__ __forceinline__ void gridsync(unsigned target) {
    __threadfence();
    __syncthreads();
    if (threadIdx.x == 0) {
        if (atomicAdd(&g_barcnt, 1) == gridDim.x - 1) {
            g_barcnt = 0;
            __threadfence();
            g_barflag = target;
        } else {
            while (g_barflag != target) __nanosleep(64);
        }
    }
    __syncthreads();
}

// ---------------- half helpers ----------------
struct Acc4 { float2 a, b; };
__device__ __forceinline__ Acc4 acc4z() { Acc4 r; r.a = make_float2(0.f,0.f); r.b = r.a; return r; }
__device__ __forceinline__ void fmah4(Acc4& A, float w, uint2 u) {
    float2 f0 = __half22float2(*reinterpret_cast<__half2*>(&u.x));
    float2 f1 = __half22float2(*reinterpret_cast<__half2*>(&u.y));
    A.a.x = fmaf(w, f0.x, A.a.x); A.a.y = fmaf(w, f0.y, A.a.y);
    A.b.x = fmaf(w, f1.x, A.b.x); A.b.y = fmaf(w, f1.y, A.b.y);
}
__device__ __forceinline__ void addh4(Acc4& A, Acc4 B) {
    A.a.x += B.a.x; A.a.y += B.a.y; A.b.x += B.b.x; A.b.y += B.b.y;
}
__device__ __forceinline__ void s2sh4(Acc4& A, uint2 t) {   // A = 2A - t
    float2 f0 = __half22float2(*reinterpret_cast<__half2*>(&t.x));
    float2 f1 = __half22float2(*reinterpret_cast<__half2*>(&t.y));
    A.a.x = fmaf(2.f, A.a.x, -f0.x); A.a.y = fmaf(2.f, A.a.y, -f0.y);
    A.b.x = fmaf(2.f, A.b.x, -f1.x); A.b.y = fmaf(2.f, A.b.y, -f1.y);
}
__device__ __forceinline__ uint2 packh4(Acc4 A) {
    uint2 r;
    *(__half2*)&r.x = __float22half2_rn(A.a);
    *(__half2*)&r.y = __float22half2_rn(A.b);
    return r;
}

// ---------------- prop phases: warp-strided over nodes ----------------
template <bool SECOND>
__device__ void prop160_phase(const __half* __restrict__ X, const __half* __restrict__ T0,
                              __half* __restrict__ out) {
    int lane = threadIdx.x & 31;
    int nw = gridDim.x << 3;
    for (int node = (blockIdx.x << 3) + (threadIdx.x >> 5); node < NN; node += nw) {
        int s = g_rowstart[node], e = g_rowstart[node + 1];
        const uint2* X4 = (const uint2*)X;
        Acc4 a0 = acc4z(), a1 = a0, a2 = a0, a3 = a0;
        Acc4 b0 = a0, b1 = a0, b2 = a0, b3 = a0;
        int j = s;
        for (; j + 3 < e; j += 4) {
            Edge e0 = g_edge[j], e1 = g_edge[j+1], e2 = g_edge[j+2], e3 = g_edge[j+3];
            long r0 = (long)e0.s * 40, r1 = (long)e1.s * 40, r2 = (long)e2.s * 40, r3 = (long)e3.s * 40;
            fmah4(a0, e0.w, X4[r0 + lane]);
            fmah4(a1, e1.w, X4[r1 + lane]);
            fmah4(a2, e2.w, X4[r2 + lane]);
            fmah4(a3, e3.w, X4[r3 + lane]);
            if (lane < 8) {
                fmah4(b0, e0.w, X4[r0 + 32 + lane]);
                fmah4(b1, e1.w, X4[r1 + 32 + lane]);
                fmah4(b2, e2.w, X4[r2 + 32 + lane]);
                fmah4(b3, e3.w, X4[r3 + 32 + lane]);
            }
        }
        for (; j < e; j++) {
            Edge e0 = g_edge[j];
            long r0 = (long)e0.s * 40;
            fmah4(a0, e0.w, X4[r0 + lane]);
            if (lane < 8) fmah4(b0, e0.w, X4[r0 + 32 + lane]);
        }
        addh4(a0, a1); addh4(a2, a3); addh4(a0, a2);
        addh4(b0, b1); addh4(b2, b3); addh4(b0, b2);
        long o = (long)node * 40;
        const uint2* T04 = (const uint2*)T0;
        if (SECOND) {
            s2sh4(a0, T04[o + lane]);
            if (lane < 8) s2sh4(b0, T04[o + 32 + lane]);
        }
        ((uint2*)out)[o + lane] = packh4(a0);
        if (lane < 8) ((uint2*)out)[o + 32 + lane] = packh4(b0);
    }
}

template <bool SECOND>
__device__ void prop128_phase(const __half* __restrict__ X, const __half* __restrict__ T0,
                              __half* __restrict__ out) {
    int lane = threadIdx.x & 31;
    int nw = gridDim.x << 3;
    for (int node = (blockIdx.x << 3) + (threadIdx.x >> 5); node < NN; node += nw) {
        int s = g_rowstart[node], e = g_rowstart[node + 1];
        const uint2* X4 = (const uint2*)X;
        Acc4 a0 = acc4z(), a1 = a0, a2 = a0, a3 = a0;
        int j = s;
        for (; j + 3 < e; j += 4) {
            Edge e0 = g_edge[j], e1 = g_edge[j+1], e2 = g_edge[j+2], e3 = g_edge[j+3];
            fmah4(a0, e0.w, X4[(long)e0.s * 32 + lane]);
            fmah4(a1, e1.w, X4[(long)e1.s * 32 + lane]);
            fmah4(a2, e2.w, X4[(long)e2.s * 32 + lane]);
            fmah4(a3, e3.w, X4[(long)e3.s * 32 + lane]);
        }
        for (; j < e; j++) {
            Edge e0 = g_edge[j];
            fmah4(a0, e0.w, X4[(long)e0.s * 32 + lane]);
        }
        addh4(a0, a1); addh4(a2, a3); addh4(a0, a2);
        long o = (long)node * 32 + lane;
        if (SECOND) s2sh4(a0, ((const uint2*)T0)[o]);
        ((uint2*)out)[o] = packh4(a0);
    }
}

template <bool SECOND>
__device__ void prop64_phase(const __half* __restrict__ X, const __half* __restrict__ T0,
                             __half* __restrict__ out) {
    int lane = threadIdx.x & 31;
    int nw = gridDim.x << 3;
    for (int node = (blockIdx.x << 3) + (threadIdx.x >> 5); node < NN; node += nw) {
        int s = g_rowstart[node], e = g_rowstart[node + 1];
        const __half2* X2 = (const __half2*)X;
        float2 a0 = make_float2(0.f,0.f), a1 = a0, a2 = a0, a3 = a0;
        int j = s;
        for (; j + 3 < e; j += 4) {
            Edge e0 = g_edge[j], e1 = g_edge[j+1], e2 = g_edge[j+2], e3 = g_edge[j+3];
            float2 f0 = __half22float2(X2[(long)e0.s * 32 + lane]);
            float2 f1 = __half22float2(X2[(long)e1.s * 32 + lane]);
            float2 f2 = __half22float2(X2[(long)e2.s * 32 + lane]);
            float2 f3 = __half22float2(X2[(long)e3.s * 32 + lane]);
            a0.x = fmaf(e0.w, f0.x, a0.x); a0.y = fmaf(e0.w, f0.y, a0.y);
            a1.x = fmaf(e1.w, f1.x, a1.x); a1.y = fmaf(e1.w, f1.y, a1.y);
            a2.x = fmaf(e2.w, f2.x, a2.x); a2.y = fmaf(e2.w, f2.y, a2.y);
            a3.x = fmaf(e3.w, f3.x, a3.x); a3.y = fmaf(e3.w, f3.y, a3.y);
        }
        for (; j < e; j++) {
            Edge e0 = g_edge[j];
            float2 f0 = __half22float2(X2[(long)e0.s * 32 + lane]);
            a0.x = fmaf(e0.w, f0.x, a0.x); a0.y = fmaf(e0.w, f0.y, a0.y);
        }
        a0.x += a1.x + a2.x + a3.x;
        a0.y += a1.y + a2.y + a3.y;
        long o = (long)node * 32 + lane;
        if (SECOND) {
            float2 t = __half22float2(((const __half2*)T0)[o]);
            a0.x = fmaf(2.f, a0.x, -t.x);
            a0.y = fmaf(2.f, a0.y, -t.y);
        }
        ((__half2*)out)[o] = __float22half2_rn(a0);
    }
}

// ---------------- tf32 MMA helpers ----------------
__device__ __forceinline__ unsigned f2tf32(float x) {
    unsigned u;
    asm("cvt.rna.tf32.f32 %0, %1;" : "=r"(u) : "f"(x));
    return u;
}
__device__ __forceinline__ void mma_tf32(float* c, const unsigned* a, unsigned b0, unsigned b1) {
    asm volatile(
        "mma.sync.aligned.m16n8k8.row.col.f32.tf32.tf32.f32 "
        "{%0,%1,%2,%3}, {%4,%5,%6,%7}, {%8,%9}, {%0,%1,%2,%3};"
        : "+f"(c[0]), "+f"(c[1]), "+f"(c[2]), "+f"(c[3])
        : "r"(a[0]), "r"(a[1]), "r"(a[2]), "r"(a[3]), "r"(b0), "r"(b1));
}
__device__ __forceinline__ float4 h4f(uint2 u) {
    float2 f0 = __half22float2(*reinterpret_cast<__half2*>(&u.x));
    float2 f1 = __half22float2(*reinterpret_cast<__half2*>(&u.y));
    return make_float4(f0.x, f0.y, f1.x, f1.y);
}

// ---------------- GEMM phase: tile-strided; out = relu([A0|A1|A2]@W + b) ----------------
template <int FIN, int FOUT, bool POOL>
__device__ void gemm_phase(const __half* __restrict__ A0, const __half* __restrict__ A1,
                           const __half* __restrict__ A2, const float* __restrict__ W,
                           const float* __restrict__ bias, __half* __restrict__ out,
                           const int* __restrict__ batch, unsigned* As, unsigned* Bs) {
    constexpr int BK = 32;
    constexpr int ASTR = 36, BSTR = FOUT + 8;
    constexpr int NCH = 3 * FIN / BK;
    constexpr int BLD = (BK * FOUT / 4) / 256;
    constexpr int NI = FOUT / 16;
    constexpr int NTILE = (NN + 127) / 128;

    int tid = threadIdx.x;
    int wp = tid >> 5, lane = tid & 31;
    int wy = wp >> 1, wx = wp & 1;
    int ly = lane >> 2, lx = lane & 3;

    for (int tile = blockIdx.x; tile < NTILE; tile += gridDim.x) {
        int row0 = tile * 128;
        float4 ar[4];
        float4 br[BLD];
        float acc[2][NI][4];
#pragma unroll
        for (int mi = 0; mi < 2; mi++)
#pragma unroll
            for (int ni = 0; ni < NI; ni++)
#pragma unroll
                for (int i = 0; i < 4; i++) acc[mi][ni][i] = 0.f;

        // load chunk 0
#pragma unroll
        for (int i = 0; i < 4; i++) {
            int idx = i * 256 + tid;
            int r = idx >> 3, k4 = (idx & 7) * 4;
            int grow = row0 + r;
            ar[i] = (grow < NN) ? h4f(*(const uint2*)&A0[(long)grow * FIN + k4])
                                : make_float4(0.f, 0.f, 0.f, 0.f);
        }
#pragma unroll
        for (int i = 0; i < BLD; i++) {
            int idx = i * 256 + tid;
            int rB = idx / (FOUT / 4);
            int n4 = (idx % (FOUT / 4)) * 4;
            br[i] = *(const float4*)&W[(long)rB * FOUT + n4];
        }

        for (int c = 0; c < NCH; c++) {
#pragma unroll
            for (int i = 0; i < 4; i++) {
                int idx = i * 256 + tid;
                int r = idx >> 3, k4 = (idx & 7) * 4;
                uint4 u;
                u.x = f2tf32(ar[i].x); u.y = f2tf32(ar[i].y);
                u.z = f2tf32(ar[i].z); u.w = f2tf32(ar[i].w);
                *(uint4*)&As[r * ASTR + k4] = u;
            }
#pragma unroll
            for (int i = 0; i < BLD; i++) {
                int idx = i * 256 + tid;
                int rB = idx / (FOUT / 4);
                int n4 = (idx % (FOUT / 4)) * 4;
                uint4 u;
                u.x = f2tf32(br[i].x); u.y = f2tf32(br[i].y);
                u.z = f2tf32(br[i].z); u.w = f2tf32(br[i].w);
                *(uint4*)&Bs[rB * BSTR + n4] = u;
            }
            __syncthreads();

            if (c + 1 < NCH) {
                int k0 = (c + 1) * BK;
                const __half* A = (k0 < FIN) ? A0 : ((k0 < 2 * FIN) ? A1 : A2);
                int kk = k0 % FIN;
#pragma unroll
                for (int i = 0; i < 4; i++) {
                    int idx = i * 256 + tid;
                    int r = idx >> 3, k4 = (idx & 7) * 4;
                    int grow = row0 + r;
                    ar[i] = (grow < NN) ? h4f(*(const uint2*)&A[(long)grow * FIN + kk + k4])
                                        : make_float4(0.f, 0.f, 0.f, 0.f);
                }
#pragma unroll
                for (int i = 0; i < BLD; i++) {
                    int idx = i * 256 + tid;
                    int rB = idx / (FOUT / 4);
                    int n4 = (idx % (FOUT / 4)) * 4;
                    br[i] = *(const float4*)&W[(long)(k0 + rB) * FOUT + n4];
                }
            }

#pragma unroll
            for (int cc = 0; cc < 4; cc++) {
                unsigned a[2][4];
#pragma unroll
                for (int mi = 0; mi < 2; mi++) {
                    int arow = wy * 32 + mi * 16 + ly;
                    int ak = cc * 8 + lx;
                    a[mi][0] = As[arow * ASTR + ak];
                    a[mi][1] = As[(arow + 8) * ASTR + ak];
                    a[mi][2] = As[arow * ASTR + ak + 4];
                    a[mi][3] = As[(arow + 8) * ASTR + ak + 4];
                }
#pragma unroll
                for (int ni = 0; ni < NI; ni++) {
                    int bn = wx * (FOUT / 2) + ni * 8 + ly;
                    unsigned b0 = Bs[(cc * 8 + lx) * BSTR + bn];
                    unsigned b1 = Bs[(cc * 8 + lx + 4) * BSTR + bn];
                    mma_tf32(acc[0][ni], a[0], b0, b1);
                    mma_tf32(acc[1][ni], a[1], b0, b1);
                }
            }
            __syncthreads();
        }

        // epilogue
#pragma unroll
        for (int mi = 0; mi < 2; mi++) {
            int r0 = row0 + wy * 32 + mi * 16 + ly;
#pragma unroll
            for (int ni = 0; ni < NI; ni++) {
                int col = wx * (FOUT / 2) + ni * 8 + lx * 2;
                float bv0 = bias[col], bv1 = bias[col + 1];
                float v00 = fmaxf(acc[mi][ni][0] + bv0, 0.f);
                float v01 = fmaxf(acc[mi][ni][1] + bv1, 0.f);
                float v10 = fmaxf(acc[mi][ni][2] + bv0, 0.f);
                float v11 = fmaxf(acc[mi][ni][3] + bv1, 0.f);
                if (!POOL) {
                    if (r0 < NN)
                        *(__half2*)&out[(long)r0 * FOUT + col] = __float22half2_rn(make_float2(v00, v01));
                    if (r0 + 8 < NN)
                        *(__half2*)&out[(long)(r0 + 8) * FOUT + col] = __float22half2_rn(make_float2(v10, v11));
                } else {
                    if (r0 < NN) {
                        int g = batch[r0];
                        atomicAdd(&g_pool[g * 32 + col], v00);
                        atomicAdd(&g_pool[g * 32 + col + 1], v01);
                    }
                    if (r0 + 8 < NN) {
                        int g = batch[r0 + 8];
                        atomicAdd(&g_pool[g * 32 + col], v10);
                        atomicAdd(&g_pool[g * 32 + col + 1], v11);
                    }
                }
            }
        }
    }
}

// ---------------- the persistent mega-kernel ----------------
union SMU {
    int scan[256];
    unsigned mm[128 * 36 + 32 * 136];   // As | Bs (max: FOUT=128)
};

__global__ void __launch_bounds__(256, 2)
mega_kernel(const float* __restrict__ x, const int* __restrict__ src,
            const int* __restrict__ dst, const float* __restrict__ ea,
            const int* __restrict__ batch,
            const float* __restrict__ W1, const float* __restrict__ b1,
            const float* __restrict__ W2, const float* __restrict__ b2,
            const float* __restrict__ W3, const float* __restrict__ b3,
            const float* __restrict__ Wl, const float* __restrict__ bl,
            float* __restrict__ out) {
    __shared__ __align__(16) SMU sm;
    unsigned* As = sm.mm;
    unsigned* Bs = sm.mm + 128 * 36;

    int tid = threadIdx.x;
    int gid = blockIdx.x * 256 + tid;
    int gsz = gridDim.x * 256;

    unsigned base = g_barflag;
    unsigned gen = 0;
#define GSYNC() gridsync(base + (++gen))

    // Phase A: zero + x -> half
    for (int i = gid; i < NN; i += gsz) { g_deg[i] = 0.f; g_count[i] = 0; }
    for (int i = gid; i < GG * 32; i += gsz) g_pool[i] = 0.f;
    for (int i = gid; i < GG; i += gsz) g_cntg[i] = 0.f;
    for (long i = gid; i < (long)NN * 40; i += gsz) {
        float4 v = ((const float4*)x)[i];
        uint2 r;
        *(__half2*)&r.x = __float22half2_rn(make_float2(v.x, v.y));
        *(__half2*)&r.y = __float22half2_rn(make_float2(v.z, v.w));
        ((uint2*)g_Xh)[i] = r;
    }
    GSYNC();

    // Phase B: degree + in-count
    for (int e = gid; e < EE; e += gsz) {
        atomicAdd(&g_deg[src[e]], ea[e]);
        atomicAdd(&g_count[dst[e]], 1);
    }
    GSYNC();

    // Phase C: chunk-local scans + dinv
    for (int c = blockIdx.x; c < NCHUNK; c += gridDim.x) {
        int i = c * 256 + tid;
        int v = (i < NN) ? g_count[i] : 0;
        sm.scan[tid] = v;
        __syncthreads();
        for (int off = 1; off < 256; off <<= 1) {
            int a = (tid >= off) ? sm.scan[tid - off] : 0;
            __syncthreads();
            sm.scan[tid] += a;
            __syncthreads();
        }
        if (i < NN) g_rs0[i] = sm.scan[tid] - v;
        if (tid == 255) g_part[c] = sm.scan[255];
        __syncthreads();
    }
    for (int i = gid; i < NN; i += gsz) {
        float d = g_deg[i];
        g_dinv[i] = (d > 0.f) ? rsqrtf(d) : 0.f;
    }
    GSYNC();

    // Phase D: scan chunk sums (block 0)
    if (blockIdx.x == 0) {
        int v = (tid < NCHUNK) ? g_part[tid] : 0;
        sm.scan[tid] = v;
        __syncthreads();
        for (int off = 1; off < 256; off <<= 1) {
            int a = (tid >= off) ? sm.scan[tid - off] : 0;
            __syncthreads();
            sm.scan[tid] += a;
            __syncthreads();
        }
        if (tid < NCHUNK) g_part[tid] = sm.scan[tid] - v;
    }
    GSYNC();

    // Phase E: finalize rowstart/cursor + per-graph counts
    for (int i = gid; i < NN; i += gsz) {
        int v = g_rs0[i] + g_part[i >> 8];
        g_rowstart[i] = v;
        g_cursor[i] = v;
        atomicAdd(&g_cntg[batch[i]], 1.f);
    }
    if (gid == 0) g_rowstart[NN] = EE;
    GSYNC();

    // Phase F: scatter edges into CSR
    for (int e = gid; e < EE; e += gsz) {
        int s = src[e], d = dst[e];
        float w = -g_dinv[s] * ea[e] * g_dinv[d];
        int pos = atomicAdd(&g_cursor[d], 1);
        Edge eg; eg.s = s; eg.w = w;
        g_edge[pos] = eg;
    }
    GSYNC();

    // Layer 1: 160 -> 128
    prop160_phase<false>(g_Xh, nullptr, g_T1a);  GSYNC();
    prop160_phase<true >(g_T1a, g_Xh, g_T2a);    GSYNC();
    gemm_phase<160, 128, false>(g_Xh, g_T1a, g_T2a, W1, b1, g_H1, nullptr, As, Bs);  GSYNC();

    // Layer 2: 128 -> 64
    prop128_phase<false>(g_H1, nullptr, g_T1b);  GSYNC();
    prop128_phase<true >(g_T1b, g_H1, g_T2b);    GSYNC();
    gemm_phase<128, 64, false>(g_H1, g_T1b, g_T2b, W2, b2, g_H2, nullptr, As, Bs);   GSYNC();

    // Layer 3: 64 -> 32 (pool fused)
    prop64_phase<false>(g_H2, nullptr, g_T1c);   GSYNC();
    prop64_phase<true >(g_T1c, g_H2, g_T2c);     GSYNC();
    gemm_phase<64, 32, true>(g_H2, g_T1c, g_T2c, W3, b3, nullptr, batch, As, Bs);    GSYNC();

    // Final linear (block 0)
    if (blockIdx.x == 0) {
        int g = tid >> 1, c = tid & 1;
        float cnt = fmaxf(g_cntg[g], 1.f);
        float inv = 1.f / cnt;
        float s = bl[c];
#pragma unroll
        for (int f = 0; f < 32; f++) s += (g_pool[g * 32 + f] * inv) * Wl[f * 2 + c];
        out[g * 2 + c] = s;
    }
#undef GSYNC
}

// ---------------- driver ----------------
extern "C" void kernel_launch(void* const* d_in, const int* in_sizes, int n_in,
                              void* d_out, int out_size) {
    const float* x     = (const float*)d_in[0];
    const int*   ei    = (const int*)d_in[1];
    const float* ea    = (const float*)d_in[2];
    const int*   batch = (const int*)d_in[3];
    const float* W1 = (const float*)d_in[4];
    const float* b1 = (const float*)d_in[5];
    const float* W2 = (const float*)d_in[6];
    const float* b2 = (const float*)d_in[7];
    const float* W3 = (const float*)d_in[8];
    const float* b3 = (const float*)d_in[9];
    const float* Wl = (const float*)d_in[10];
    const float* bl = (const float*)d_in[11];
    float* out = (float*)d_out;

    const int* src = ei;
    const int* dst = ei + EE;

    int dev = 0, nsm = 148, maxb = 1;
    cudaGetDevice(&dev);
    cudaDeviceGetAttribute(&nsm, cudaDevAttrMultiProcessorCount, dev);
    cudaOccupancyMaxActiveBlocksPerMultiprocessor(&maxb, mega_kernel, 256, 0);
    if (maxb < 1) maxb = 1;
    if (maxb > 2) maxb = 2;
    int grid = nsm * maxb;

    mega_kernel<<<grid, 256>>>(x, src, dst, ea, batch,
                               W1, b1, W2, b2, W3, b3, Wl, bl, out);
}

// round 8
// speedup vs baseline: 1.3875x; 1.3875x over previous
#include <cuda_runtime.h>
#include <cuda_fp16.h>

#define NN 50000
#define EE 500000
#define GG 128
#define SCAN_B 512
#define NBLK ((NN + SCAN_B - 1) / SCAN_B)   // 98

struct __align__(8) Edge { int s; float w; };

// ---------------- scratch (static device allocations) ----------------
__device__ float g_deg[NN];
__device__ float g_dinv[NN];
__device__ int   g_count[NN];
__device__ int   g_rowstart[NN + 1];
__device__ int   g_cursor[NN];
__device__ int   g_part[NBLK];
__device__ Edge  g_edge[EE];

__device__ __half g_Xh[NN * 160];
__device__ __half g_T1[NN * 160];
__device__ __half g_T2[NN * 160];
__device__ __half g_H1[NN * 128];
__device__ __half g_H2[NN * 64];
__device__ float  g_pool[GG * 32];
__device__ float  g_cntg[GG];

// ---------------- preprocessing ----------------
// zero + x->half fused (independent index ranges)
__global__ void zero_conv_kernel(const float* __restrict__ x) {
    long i = (long)blockIdx.x * blockDim.x + threadIdx.x;
    if (i < NN) { g_deg[i] = 0.f; g_count[i] = 0; }
    if (i < GG * 32) g_pool[i] = 0.f;
    if (i < GG) g_cntg[i] = 0.f;
    if (i < (long)NN * 40) {
        float4 v = ((const float4*)x)[i];
        uint2 r;
        *(__half2*)&r.x = __float22half2_rn(make_float2(v.x, v.y));
        *(__half2*)&r.y = __float22half2_rn(make_float2(v.z, v.w));
        ((uint2*)g_Xh)[i] = r;
    }
}

__global__ void edge_deg_kernel(const int* __restrict__ src, const int* __restrict__ dst,
                                const float* __restrict__ ea) {
    int e = blockIdx.x * blockDim.x + threadIdx.x;
    if (e >= EE) return;
    atomicAdd(&g_deg[src[e]], ea[e]);
    atomicAdd(&g_count[dst[e]], 1);
}

__global__ void scan1_kernel() {
    __shared__ int s[SCAN_B];
    int t = threadIdx.x;
    int i = blockIdx.x * SCAN_B + t;
    int v = (i < NN) ? g_count[i] : 0;
    s[t] = v;
    __syncthreads();
    for (int off = 1; off < SCAN_B; off <<= 1) {
        int add = (t >= off) ? s[t - off] : 0;
        __syncthreads();
        s[t] += add;
        __syncthreads();
    }
    if (i < NN) g_rowstart[i] = s[t] - v;   // exclusive within block
    if (t == SCAN_B - 1) g_part[blockIdx.x] = s[t];
}

__global__ void scan2_kernel() {
    __shared__ int s[128];
    int t = threadIdx.x;
    int v = (t < NBLK) ? g_part[t] : 0;
    s[t] = v;
    __syncthreads();
    for (int off = 1; off < 128; off <<= 1) {
        int a = (t >= off) ? s[t - off] : 0;
        __syncthreads();
        s[t] += a;
        __syncthreads();
    }
    if (t < NBLK) g_part[t] = s[t] - v;     // exclusive block offsets
}

// scan3 + dinv + per-graph node count (fused)
__global__ void scan3_kernel(const int* __restrict__ batch) {
    int i = blockIdx.x * blockDim.x + threadIdx.x;
    if (i < NN) {
        int v = g_rowstart[i] + g_part[i / SCAN_B];
        g_rowstart[i] = v;
        g_cursor[i] = v;
        float d = g_deg[i];
        g_dinv[i] = (d > 0.f) ? rsqrtf(d) : 0.f;
        atomicAdd(&g_cntg[batch[i]], 1.f);
    }
    if (i == 0) g_rowstart[NN] = EE;
}

__global__ void edge_scatter_kernel(const int* __restrict__ src, const int* __restrict__ dst,
                                    const float* __restrict__ ea) {
    int e = blockIdx.x * blockDim.x + threadIdx.x;
    if (e >= EE) return;
    int s = src[e], d = dst[e];
    float w = -g_dinv[s] * ea[e] * g_dinv[d];
    int pos = atomicAdd(&g_cursor[d], 1);
    Edge eg; eg.s = s; eg.w = w;
    g_edge[pos] = eg;
}

// ---------------- half helpers ----------------
struct Acc4 { float2 a, b; };
__device__ __forceinline__ Acc4 acc4z() { Acc4 r; r.a = make_float2(0.f,0.f); r.b = r.a; return r; }
__device__ __forceinline__ void fmah4(Acc4& A, float w, uint2 u) {
    float2 f0 = __half22float2(*reinterpret_cast<__half2*>(&u.x));
    float2 f1 = __half22float2(*reinterpret_cast<__half2*>(&u.y));
    A.a.x = fmaf(w, f0.x, A.a.x); A.a.y = fmaf(w, f0.y, A.a.y);
    A.b.x = fmaf(w, f1.x, A.b.x); A.b.y = fmaf(w, f1.y, A.b.y);
}
__device__ __forceinline__ void addh4(Acc4& A, Acc4 B) {
    A.a.x += B.a.x; A.a.y += B.a.y; A.b.x += B.b.x; A.b.y += B.b.y;
}
__device__ __forceinline__ void s2sh4(Acc4& A, uint2 t) {   // A = 2A - t
    float2 f0 = __half22float2(*reinterpret_cast<__half2*>(&t.x));
    float2 f1 = __half22float2(*reinterpret_cast<__half2*>(&t.y));
    A.a.x = fmaf(2.f, A.a.x, -f0.x); A.a.y = fmaf(2.f, A.a.y, -f0.y);
    A.b.x = fmaf(2.f, A.b.x, -f1.x); A.b.y = fmaf(2.f, A.b.y, -f1.y);
}
__device__ __forceinline__ uint2 packh4(Acc4 A) {
    uint2 r;
    *(__half2*)&r.x = __float22half2_rn(A.a);
    *(__half2*)&r.y = __float22half2_rn(A.b);
    return r;
}

// ---------------- sparse propagate: warp per node, 2-way ILP, high occupancy ----------------
template <bool SECOND>
__global__ void __launch_bounds__(256, 5)
prop160h(const __half* __restrict__ X, const __half* __restrict__ T0, __half* __restrict__ out) {
    int node = (blockIdx.x << 3) + (threadIdx.x >> 5);
    if (node >= NN) return;
    int lane = threadIdx.x & 31;
    int s = g_rowstart[node], e = g_rowstart[node + 1];
    const uint2* X4 = (const uint2*)X;
    Acc4 a0 = acc4z(), a1 = a0, b0 = a0, b1 = a0;
    int j = s;
    for (; j + 1 < e; j += 2) {
        Edge e0 = g_edge[j], e1 = g_edge[j+1];
        long r0 = (long)e0.s * 40, r1 = (long)e1.s * 40;
        fmah4(a0, e0.w, X4[r0 + lane]);
        fmah4(a1, e1.w, X4[r1 + lane]);
        if (lane < 8) {
            fmah4(b0, e0.w, X4[r0 + 32 + lane]);
            fmah4(b1, e1.w, X4[r1 + 32 + lane]);
        }
    }
    if (j < e) {
        Edge e0 = g_edge[j];
        long r0 = (long)e0.s * 40;
        fmah4(a0, e0.w, X4[r0 + lane]);
        if (lane < 8) fmah4(b0, e0.w, X4[r0 + 32 + lane]);
    }
    addh4(a0, a1);
    addh4(b0, b1);
    long o = (long)node * 40;
    const uint2* T04 = (const uint2*)T0;
    if (SECOND) {
        s2sh4(a0, T04[o + lane]);
        if (lane < 8) s2sh4(b0, T04[o + 32 + lane]);
    }
    ((uint2*)out)[o + lane] = packh4(a0);
    if (lane < 8) ((uint2*)out)[o + 32 + lane] = packh4(b0);
}

template <bool SECOND>
__global__ void __launch_bounds__(256, 5)
prop128h(const __half* __restrict__ X, const __half* __restrict__ T0, __half* __restrict__ out) {
    int node = (blockIdx.x << 3) + (threadIdx.x >> 5);
    if (node >= NN) return;
    int lane = threadIdx.x & 31;
    int s = g_rowstart[node], e = g_rowstart[node + 1];
    const uint2* X4 = (const uint2*)X;
    Acc4 a0 = acc4z(), a1 = a0;
    int j = s;
    for (; j + 1 < e; j += 2) {
        Edge e0 = g_edge[j], e1 = g_edge[j+1];
        fmah4(a0, e0.w, X4[(long)e0.s * 32 + lane]);
        fmah4(a1, e1.w, X4[(long)e1.s * 32 + lane]);
    }
    if (j < e) {
        Edge e0 = g_edge[j];
        fmah4(a0, e0.w, X4[(long)e0.s * 32 + lane]);
    }
    addh4(a0, a1);
    long o = (long)node * 32 + lane;
    if (SECOND) s2sh4(a0, ((const uint2*)T0)[o]);
    ((uint2*)out)[o] = packh4(a0);
}

template <bool SECOND>
__global__ void __launch_bounds__(256, 5)
prop64h(const __half* __restrict__ X, const __half* __restrict__ T0, __half* __restrict__ out) {
    int node = (blockIdx.x << 3) + (threadIdx.x >> 5);
    if (node >= NN) return;
    int lane = threadIdx.x & 31;
    int s = g_rowstart[node], e = g_rowstart[node + 1];
    const __half2* X2 = (const __half2*)X;
    float2 a0 = make_float2(0.f,0.f), a1 = a0;
    int j = s;
    for (; j + 1 < e; j += 2) {
        Edge e0 = g_edge[j], e1 = g_edge[j+1];
        float2 f0 = __half22float2(X2[(long)e0.s * 32 + lane]);
        float2 f1 = __half22float2(X2[(long)e1.s * 32 + lane]);
        a0.x = fmaf(e0.w, f0.x, a0.x); a0.y = fmaf(e0.w, f0.y, a0.y);
        a1.x = fmaf(e1.w, f1.x, a1.x); a1.y = fmaf(e1.w, f1.y, a1.y);
    }
    if (j < e) {
        Edge e0 = g_edge[j];
        float2 f0 = __half22float2(X2[(long)e0.s * 32 + lane]);
        a0.x = fmaf(e0.w, f0.x, a0.x); a0.y = fmaf(e0.w, f0.y, a0.y);
    }
    a0.x += a1.x; a0.y += a1.y;
    long o = (long)node * 32 + lane;
    if (SECOND) {
        float2 t = __half22float2(((const __half2*)T0)[o]);
        a0.x = fmaf(2.f, a0.x, -t.x);
        a0.y = fmaf(2.f, a0.y, -t.y);
    }
    ((__half2*)out)[o] = __float22half2_rn(a0);
}

// ---------------- tf32 MMA helpers ----------------
__device__ __forceinline__ unsigned f2tf32(float x) {
    unsigned u;
    asm("cvt.rna.tf32.f32 %0, %1;" : "=r"(u) : "f"(x));
    return u;
}
__device__ __forceinline__ void mma_tf32(float* c, const unsigned* a, unsigned b0, unsigned b1) {
    asm volatile(
        "mma.sync.aligned.m16n8k8.row.col.f32.tf32.tf32.f32 "
        "{%0,%1,%2,%3}, {%4,%5,%6,%7}, {%8,%9}, {%0,%1,%2,%3};"
        : "+f"(c[0]), "+f"(c[1]), "+f"(c[2]), "+f"(c[3])
        : "r"(a[0]), "r"(a[1]), "r"(a[2]), "r"(a[3]), "r"(b0), "r"(b1));
}
__device__ __forceinline__ float4 h4f(uint2 u) {
    float2 f0 = __half22float2(*reinterpret_cast<__half2*>(&u.x));
    float2 f1 = __half22float2(*reinterpret_cast<__half2*>(&u.y));
    return make_float4(f0.x, f0.y, f1.x, f1.y);
}

// ---------------- tf32 fused 3-term GEMM: BM=64, 4m x 2n warps, <=64 regs ----------------
// out = relu([A0|A1|A2] @ W + bias); POOL: atomicAdd into g_pool by batch instead.
template <int FIN, int FOUT, bool POOL>
__global__ void __launch_bounds__(256, 4)
gemm3_mma(const __half* __restrict__ A0, const __half* __restrict__ A1,
          const __half* __restrict__ A2, const float* __restrict__ W,
          const float* __restrict__ bias, __half* __restrict__ out,
          const int* __restrict__ batch) {
    constexpr int BM = 64, BK = 32;
    constexpr int ASTR = 36, BSTR = FOUT + 8;
    constexpr int NCH = 3 * FIN / BK;
    constexpr int BLD = (BK * FOUT / 4) / 256;  // B float4 per thread
    constexpr int NI = FOUT / 16;               // n8 tiles per warp (warp tile 16 x FOUT/2)
    __shared__ unsigned As[BM * ASTR];
    __shared__ unsigned Bs[BK * BSTR];

    int tid = threadIdx.x;
    int wp = tid >> 5, lane = tid & 31;
    int wy = wp >> 1, wx = wp & 1;       // 4 x 2 warp grid
    int ly = lane >> 2, lx = lane & 3;
    int row0 = blockIdx.x * BM;

    float acc[NI][4];
#pragma unroll
    for (int ni = 0; ni < NI; ni++)
#pragma unroll
        for (int i = 0; i < 4; i++) acc[ni][i] = 0.f;

    for (int c = 0; c < NCH; c++) {
        int k0 = c * BK;
        const __half* A = (k0 < FIN) ? A0 : ((k0 < 2 * FIN) ? A1 : A2);
        int kk = k0 % FIN;
        // A tile: 64 x 32 floats = 512 float4, 2 per thread
#pragma unroll
        for (int i = 0; i < 2; i++) {
            int idx = i * 256 + tid;
            int r = idx >> 3, k4 = (idx & 7) * 4;
            int grow = row0 + r;
            float4 v = (grow < NN) ? h4f(*(const uint2*)&A[(long)grow * FIN + kk + k4])
                                   : make_float4(0.f, 0.f, 0.f, 0.f);
            uint4 u;
            u.x = f2tf32(v.x); u.y = f2tf32(v.y); u.z = f2tf32(v.z); u.w = f2tf32(v.w);
            *(uint4*)&As[r * ASTR + k4] = u;
        }
        // B tile: BK x FOUT from W
#pragma unroll
        for (int i = 0; i < BLD; i++) {
            int idx = i * 256 + tid;
            int rB = idx / (FOUT / 4);
            int n4 = (idx % (FOUT / 4)) * 4;
            float4 v = *(const float4*)&W[(long)(k0 + rB) * FOUT + n4];
            uint4 u;
            u.x = f2tf32(v.x); u.y = f2tf32(v.y); u.z = f2tf32(v.z); u.w = f2tf32(v.w);
            *(uint4*)&Bs[rB * BSTR + n4] = u;
        }
        __syncthreads();

#pragma unroll
        for (int cc = 0; cc < 4; cc++) {
            unsigned a[4];
            int arow = wy * 16 + ly;
            int ak = cc * 8 + lx;
            a[0] = As[arow * ASTR + ak];
            a[1] = As[(arow + 8) * ASTR + ak];
            a[2] = As[arow * ASTR + ak + 4];
            a[3] = As[(arow + 8) * ASTR + ak + 4];
#pragma unroll
            for (int ni = 0; ni < NI; ni++) {
                int bn = wx * (FOUT / 2) + ni * 8 + ly;
                unsigned b0 = Bs[(cc * 8 + lx) * BSTR + bn];
                unsigned b1 = Bs[(cc * 8 + lx + 4) * BSTR + bn];
                mma_tf32(acc[ni], a, b0, b1);
            }
        }
        __syncthreads();
    }

    // epilogue
    int r0 = row0 + wy * 16 + ly;
#pragma unroll
    for (int ni = 0; ni < NI; ni++) {
        int col = wx * (FOUT / 2) + ni * 8 + lx * 2;
        float bv0 = bias[col], bv1 = bias[col + 1];
        float v00 = fmaxf(acc[ni][0] + bv0, 0.f);
        float v01 = fmaxf(acc[ni][1] + bv1, 0.f);
        float v10 = fmaxf(acc[ni][2] + bv0, 0.f);
        float v11 = fmaxf(acc[ni][3] + bv1, 0.f);
        if (!POOL) {
            if (r0 < NN)
                *(__half2*)&out[(long)r0 * FOUT + col] = __float22half2_rn(make_float2(v00, v01));
            if (r0 + 8 < NN)
                *(__half2*)&out[(long)(r0 + 8) * FOUT + col] = __float22half2_rn(make_float2(v10, v11));
        } else {
            if (r0 < NN) {
                int g = batch[r0];
                atomicAdd(&g_pool[g * 32 + col], v00);
                atomicAdd(&g_pool[g * 32 + col + 1], v01);
            }
            if (r0 + 8 < NN) {
                int g = batch[r0 + 8];
                atomicAdd(&g_pool[g * 32 + col], v10);
                atomicAdd(&g_pool[g * 32 + col + 1], v11);
            }
        }
    }
}

// ---------------- final linear ----------------
__global__ void final_kernel(const float* __restrict__ Wl, const float* __restrict__ bl,
                             float* __restrict__ out) {
    int t = threadIdx.x;
    if (t >= GG * 2) return;
    int g = t >> 1, c = t & 1;
    float cnt = fmaxf(g_cntg[g], 1.f);
    float inv = 1.f / cnt;
    float s = bl[c];
#pragma unroll
    for (int f = 0; f < 32; f++) s += (g_pool[g * 32 + f] * inv) * Wl[f * 2 + c];
    out[g * 2 + c] = s;
}

// ---------------- driver ----------------
extern "C" void kernel_launch(void* const* d_in, const int* in_sizes, int n_in,
                              void* d_out, int out_size) {
    const float* x     = (const float*)d_in[0];
    const int*   ei    = (const int*)d_in[1];
    const float* ea    = (const float*)d_in[2];
    const int*   batch = (const int*)d_in[3];
    const float* W1 = (const float*)d_in[4];
    const float* b1 = (const float*)d_in[5];
    const float* W2 = (const float*)d_in[6];
    const float* b2 = (const float*)d_in[7];
    const float* W3 = (const float*)d_in[8];
    const float* b3 = (const float*)d_in[9];
    const float* Wl = (const float*)d_in[10];
    const float* bl = (const float*)d_in[11];
    float* out = (float*)d_out;

    const int* src = ei;
    const int* dst = ei + EE;

    __half *Xh, *T1, *T2, *H1, *H2;
    cudaGetSymbolAddress((void**)&Xh, g_Xh);
    cudaGetSymbolAddress((void**)&T1, g_T1);
    cudaGetSymbolAddress((void**)&T2, g_T2);
    cudaGetSymbolAddress((void**)&H1, g_H1);
    cudaGetSymbolAddress((void**)&H2, g_H2);

    int eb = (EE + 255) / 256;
    int pb = (NN + 7) / 8;             // warp-per-node prop grid
    int gb = (NN + 63) / 64;           // gemm grid (BM=64)
    int zb = ((NN * 40) + 255) / 256;  // zero+convert grid
    int nb = (NN + 255) / 256;

    zero_conv_kernel<<<zb, 256>>>(x);
    edge_deg_kernel<<<eb, 256>>>(src, dst, ea);
    scan1_kernel<<<NBLK, SCAN_B>>>();
    scan2_kernel<<<1, 128>>>();
    scan3_kernel<<<nb, 256>>>(batch);
    edge_scatter_kernel<<<eb, 256>>>(src, dst, ea);

    // Layer 1: 160 -> 128
    prop160h<false><<<pb, 256>>>(Xh, nullptr, T1);
    prop160h<true ><<<pb, 256>>>(T1, Xh, T2);
    gemm3_mma<160, 128, false><<<gb, 256>>>(Xh, T1, T2, W1, b1, H1, nullptr);

    // Layer 2: 128 -> 64
    prop128h<false><<<pb, 256>>>(H1, nullptr, T1);
    prop128h<true ><<<pb, 256>>>(T1, H1, T2);
    gemm3_mma<128, 64, false><<<gb, 256>>>(H1, T1, T2, W2, b2, H2, nullptr);

    // Layer 3: 64 -> 32  (pooling fused into epilogue)
    prop64h<false><<<pb, 256>>>(H2, nullptr, T1);
    prop64h<true ><<<pb, 256>>>(T1, H2, T2);
    gemm3_mma<64, 32, true><<<gb, 256>>>(H2, T1, T2, W3, b3, nullptr, batch);

    // Final linear
    final_kernel<<<1, 256>>>(Wl, bl, out);
}